// round 5
// baseline (speedup 1.0000x reference)
#include <cuda_runtime.h>
#include <math.h>

#define NN 50000
#define EE 800000
#define NEG 0.2f

// ---------------- static device scratch (no allocations) ----------------
__device__ __align__(16) float g_xl[(size_t)NN * 128];
__device__ __align__(16) float g_xr[(size_t)NN * 128];
__device__ __align__(16) float g_h [(size_t)NN * 128];
__device__ __align__(16) float g_em1[(size_t)EE * 128];
__device__ __align__(16) float g_alpha[(size_t)EE * 8];   // logits, then alpha in-place
__device__ float g_mx[NN * 8];
__device__ float g_den[NN * 8];
__device__ int   g_rowptr[NN + 1];
__device__ int   g_deg[NN];
__device__ int   g_perm[EE];
__device__ __align__(16) float g_cw[4 * 64 * 128];  // up_W@{Wl0,Wr0,We0,We1}
__device__ float g_cb[4 * 128];

__device__ __forceinline__ float f4c(const float4& v, int k) {
    return k == 0 ? v.x : k == 1 ? v.y : k == 2 ? v.z : v.w;
}

// ---------------- CSR build ----------------
__global__ void mt_zero_int(int* p, int n) {
    int i = blockIdx.x * blockDim.x + threadIdx.x;
    if (i < n) p[i] = 0;
}
__global__ void mt_hist(const int* __restrict__ dst, int e) {
    int i = blockIdx.x * blockDim.x + threadIdx.x;
    if (i < e) atomicAdd(&g_deg[dst[i]], 1);
}
__global__ void mt_scan(int n) {
    __shared__ int sh[1024];
    int t = threadIdx.x;
    int carry = 0;
    for (int base = 0; base < n; base += 1024) {
        int idx = base + t;
        int v = (idx < n) ? g_deg[idx] : 0;
        sh[t] = v;
        __syncthreads();
        for (int off = 1; off < 1024; off <<= 1) {
            int u = (t >= off) ? sh[t - off] : 0;
            __syncthreads();
            sh[t] += u;
            __syncthreads();
        }
        if (idx < n) {
            int excl = sh[t] - v;
            g_rowptr[idx] = carry + excl;
            g_deg[idx]    = carry + excl;   // scatter cursor
        }
        carry += sh[1023];
        __syncthreads();
    }
    if (t == 0) g_rowptr[n] = carry;
}
__global__ void mt_scatter(const int* __restrict__ dst, int e) {
    int i = blockIdx.x * blockDim.x + threadIdx.x;
    if (i < e) {
        int p = atomicAdd(&g_deg[dst[i]], 1);
        g_perm[p] = i;
    }
}

// ---------------- fold up_W into block weights ----------------
__global__ void mt_combine(const float* __restrict__ up_W, const float* __restrict__ up_b,
                           const float* __restrict__ Wl0, const float* __restrict__ bl0,
                           const float* __restrict__ Wr0, const float* __restrict__ br0,
                           const float* __restrict__ We0, const float* __restrict__ We1) {
    __shared__ float row[128];
    int c = threadIdx.x;
    int k = blockIdx.x;
    if (k < 64) {
        row[c] = up_W[k * 128 + c];
        __syncthreads();
        float a0 = 0.f, a1 = 0.f, a2 = 0.f, a3 = 0.f;
        for (int j = 0; j < 128; j++) {
            float r = row[j];
            a0 += r * Wl0[j * 128 + c];
            a1 += r * Wr0[j * 128 + c];
            a2 += r * We0[j * 128 + c];
            a3 += r * We1[j * 128 + c];
        }
        g_cw[0 * 64 * 128 + k * 128 + c] = a0;
        g_cw[1 * 64 * 128 + k * 128 + c] = a1;
        g_cw[2 * 64 * 128 + k * 128 + c] = a2;
        g_cw[3 * 64 * 128 + k * 128 + c] = a3;
    } else {
        float a0 = 0.f, a1 = 0.f, a2 = 0.f, a3 = 0.f;
        for (int j = 0; j < 128; j++) {
            float ub = up_b[j];
            a0 += ub * Wl0[j * 128 + c];
            a1 += ub * Wr0[j * 128 + c];
            a2 += ub * We0[j * 128 + c];
            a3 += ub * We1[j * 128 + c];
        }
        g_cb[0 * 128 + c] = a0 + bl0[c];
        g_cb[1 * 128 + c] = a1 + br0[c];
        g_cb[2 * 128 + c] = a2;
        g_cb[3 * 128 + c] = a3;
    }
}

// ---------------- row GEMM: out[rows,128] = in[rows,K]@W + bias ----------------
template <int K>
__global__ void __launch_bounds__(128)
mt_gemm(const float* __restrict__ in, const float* __restrict__ W,
        const float* __restrict__ bias, int sel, float* __restrict__ out, int rows) {
    extern __shared__ float sm[];
    float* Ws = sm;             // K*128
    float* As = sm + K * 128;   // 8*K
    const float* Wp = W ? W : g_cw + sel * 64 * 128;
    const float* bp = bias ? bias : g_cb + sel * 128;
    int c = threadIdx.x;
    for (int i = c; i < K * 128; i += 128) Ws[i] = Wp[i];
    float bv = bp[c];
    int ntiles = (rows + 7) >> 3;
    for (int t = blockIdx.x; t < ntiles; t += gridDim.x) {
        int rb = t << 3;
        __syncthreads();
        for (int i = c; i < 8 * K; i += 128) {
            int gi = rb * K + i;
            As[i] = (gi < rows * K) ? in[gi] : 0.f;
        }
        __syncthreads();
        float acc[8];
#pragma unroll
        for (int r = 0; r < 8; r++) acc[r] = bv;
        const float4* As4 = reinterpret_cast<const float4*>(As);
#pragma unroll 4
        for (int k4 = 0; k4 < K / 4; k4++) {
            float4 a[8];
#pragma unroll
            for (int r = 0; r < 8; r++) a[r] = As4[r * (K / 4) + k4];
#pragma unroll
            for (int kk = 0; kk < 4; kk++) {
                float w = Ws[(k4 * 4 + kk) * 128 + c];
#pragma unroll
                for (int r = 0; r < 8; r++) acc[r] += f4c(a[r], kk) * w;
            }
        }
        int nr = min(8, rows - rb);
#pragma unroll
        for (int r = 0; r < 8; r++)
            if (r < nr) out[(size_t)(rb + r) * 128 + c] = acc[r];
    }
}

// ---------------- fused block-0 edge kernel: em0->logits, em1 stored ----------------
__global__ void __launch_bounds__(128)
mt_edge_block0(const float* __restrict__ ef, const int* __restrict__ src,
               const int* __restrict__ dst, const float* __restrict__ att) {
    extern __shared__ float sm[];
    float* WsA = sm;                 // 64*128 (cw2: We0 fold)
    float* WsB = sm + 64 * 128;      // 64*128 (cw3: We1 fold)
    float* As  = sm + 2 * 64 * 128;  // 8*64
    __shared__ float s_att[128];
    __shared__ int sidx[8], didx[8];
    int c = threadIdx.x;
    for (int i = c; i < 64 * 128; i += 128) {
        WsA[i] = g_cw[2 * 64 * 128 + i];
        WsB[i] = g_cw[3 * 64 * 128 + i];
    }
    s_att[c] = att[c];
    float cb2 = g_cb[2 * 128 + c], cb3 = g_cb[3 * 128 + c];
    int ntiles = (EE + 7) >> 3;
    for (int t = blockIdx.x; t < ntiles; t += gridDim.x) {
        int rb = t << 3;
        int nr = min(8, EE - rb);
        __syncthreads();
        if (c < nr) { sidx[c] = src[rb + c]; didx[c] = dst[rb + c]; }
        for (int i = c; i < 8 * 64; i += 128) {
            int gi = rb * 64 + i;
            As[i] = (gi < EE * 64) ? ef[gi] : 0.f;
        }
        __syncthreads();
        float acc0[8], acc1[8];
#pragma unroll
        for (int r = 0; r < 8; r++) { acc0[r] = cb2; acc1[r] = cb3; }
        const float4* As4 = reinterpret_cast<const float4*>(As);
#pragma unroll 4
        for (int k4 = 0; k4 < 16; k4++) {
            float4 a[8];
#pragma unroll
            for (int r = 0; r < 8; r++) a[r] = As4[r * 16 + k4];
#pragma unroll
            for (int kk = 0; kk < 4; kk++) {
                float wA = WsA[(k4 * 4 + kk) * 128 + c];
                float wB = WsB[(k4 * 4 + kk) * 128 + c];
#pragma unroll
                for (int r = 0; r < 8; r++) {
                    float av = f4c(a[r], kk);
                    acc0[r] += av * wA;
                    acc1[r] += av * wB;
                }
            }
        }
#pragma unroll
        for (int r = 0; r < 8; r++) {
            if (r < nr) {
                int e = rb + r;
                g_em1[(size_t)e * 128 + c] = acc1[r];
                float m = acc0[r] + g_xl[(size_t)sidx[r] * 128 + c]
                                  + g_xr[(size_t)didx[r] * 128 + c];
                m = m > 0.f ? m : NEG * m;
                float p = m * s_att[c];
                p += __shfl_xor_sync(0xffffffffu, p, 8, 16);
                p += __shfl_xor_sync(0xffffffffu, p, 4, 16);
                p += __shfl_xor_sync(0xffffffffu, p, 2, 16);
                p += __shfl_xor_sync(0xffffffffu, p, 1, 16);
                if ((c & 15) == 0) g_alpha[(size_t)e * 8 + (c >> 4)] = p;
            }
        }
    }
}

// ---------------- block-1 edge logits (memory-bound stream over em1) ----------------
__global__ void __launch_bounds__(128)
mt_edge_logits1(const int* __restrict__ src, const int* __restrict__ dst,
                const float* __restrict__ att) {
    __shared__ float s_att[128];
    __shared__ int sidx[8], didx[8];
    int c = threadIdx.x;
    s_att[c] = att[c];
    int rb = blockIdx.x * 8;
    int nr = min(8, EE - rb);
    if (c < nr) { sidx[c] = src[rb + c]; didx[c] = dst[rb + c]; }
    __syncthreads();
    for (int r = 0; r < nr; r++) {
        int e = rb + r;
        float m = g_em1[(size_t)e * 128 + c] + g_xl[(size_t)sidx[r] * 128 + c]
                                             + g_xr[(size_t)didx[r] * 128 + c];
        m = m > 0.f ? m : NEG * m;
        float p = m * s_att[c];
        p += __shfl_xor_sync(0xffffffffu, p, 8, 16);
        p += __shfl_xor_sync(0xffffffffu, p, 4, 16);
        p += __shfl_xor_sync(0xffffffffu, p, 2, 16);
        p += __shfl_xor_sync(0xffffffffu, p, 1, 16);
        if ((c & 15) == 0) g_alpha[(size_t)e * 8 + (c >> 4)] = p;
    }
}

// ---------------- segment softmax: per-(node,head) online max+den ----------------
__global__ void mt_softmax_stats() {
    int t = threadIdx.x;
    int n = blockIdx.x * 16 + (t >> 3);
    int h = t & 7;
    if (n >= NN) return;
    int beg = g_rowptr[n], end = g_rowptr[n + 1];
    float mx = -1e30f, den = 0.f;
    for (int j = beg; j < end; j++) {
        int e = g_perm[j];
        float lg = g_alpha[(size_t)e * 8 + h];
        if (lg > mx) { den *= __expf(mx - lg); mx = lg; }
        den += __expf(lg - mx);
    }
    g_mx[n * 8 + h] = mx;
    g_den[n * 8 + h] = den;
}

__global__ void mt_alpha(const int* __restrict__ dst) {
    int i = blockIdx.x * blockDim.x + threadIdx.x;
    if (i < EE * 8) {
        int e = i >> 3, h = i & 7;
        int d = dst[e];
        g_alpha[i] = __expf(g_alpha[i] - g_mx[d * 8 + h]) / g_den[d * 8 + h];
    }
}

// ---------------- aggregate + bias + LayerNorm + ReLU ----------------
__global__ void __launch_bounds__(128)
mt_aggregate(const int* __restrict__ src, const float* __restrict__ bias,
             const float* __restrict__ ls, const float* __restrict__ lb,
             const float* __restrict__ xl, float* __restrict__ out) {
    __shared__ int sidx[16];
    __shared__ int eidx[16];
    __shared__ float sal[16 * 8];
    __shared__ float red[8];
    int n = blockIdx.x;
    int c = threadIdx.x;
    int h = c >> 4;
    int beg = g_rowptr[n], cnt = g_rowptr[n + 1] - beg;
    float acc = 0.f;
    for (int off = 0; off < cnt; off += 16) {
        int cl = min(16, cnt - off);
        __syncthreads();
        if (c < cl) {
            int e = g_perm[beg + off + c];
            eidx[c] = e;
            sidx[c] = src[e];
        }
        __syncthreads();
        if ((c >> 3) < cl) sal[c] = g_alpha[(size_t)eidx[c >> 3] * 8 + (c & 7)];
        __syncthreads();
        for (int i = 0; i < cl; i++)
            acc += sal[i * 8 + h] * xl[(size_t)sidx[i] * 128 + c];
    }
    float o = acc + bias[c];
    float s1 = o, s2 = o * o;
#pragma unroll
    for (int off = 16; off; off >>= 1) {
        s1 += __shfl_xor_sync(0xffffffffu, s1, off);
        s2 += __shfl_xor_sync(0xffffffffu, s2, off);
    }
    if ((c & 31) == 0) { red[c >> 5] = s1; red[4 + (c >> 5)] = s2; }
    __syncthreads();
    s1 = red[0] + red[1] + red[2] + red[3];
    s2 = red[4] + red[5] + red[6] + red[7];
    float mu = s1 * (1.f / 128.f);
    float var = s2 * (1.f / 128.f) - mu * mu;
    o = (o - mu) * rsqrtf(var + 1e-5f) * ls[c] + lb[c];
    out[(size_t)n * 128 + c] = fmaxf(o, 0.f);
}

// ---------------- node head: softmax(h@node_W+b) ----------------
__global__ void __launch_bounds__(128)
mt_node_head(const float* __restrict__ hh, const float* __restrict__ W,
             const float* __restrict__ b, float* __restrict__ out) {
    __shared__ float Ws[128 * 8];
    __shared__ float sb[8];
    int t = threadIdx.x, lane = t & 31, wid = t >> 5;
    for (int i = t; i < 1024; i += 128) Ws[i] = W[i];
    if (t < 8) sb[t] = b[t];
    __syncthreads();
    int n = blockIdx.x * 4 + wid;
    if (n >= NN) return;
    float4 hv = reinterpret_cast<const float4*>(hh + (size_t)n * 128)[lane];
    float a[8];
#pragma unroll
    for (int k = 0; k < 8; k++)
        a[k] = hv.x * Ws[(lane * 4 + 0) * 8 + k] + hv.y * Ws[(lane * 4 + 1) * 8 + k]
             + hv.z * Ws[(lane * 4 + 2) * 8 + k] + hv.w * Ws[(lane * 4 + 3) * 8 + k];
#pragma unroll
    for (int k = 0; k < 8; k++)
#pragma unroll
        for (int off = 16; off; off >>= 1) a[k] += __shfl_xor_sync(0xffffffffu, a[k], off);
    if (lane == 0) {
        float mx = -1e30f;
#pragma unroll
        for (int k = 0; k < 8; k++) { a[k] += sb[k]; mx = fmaxf(mx, a[k]); }
        float e[8], den = 0.f;
#pragma unroll
        for (int k = 0; k < 8; k++) { e[k] = __expf(a[k] - mx); den += e[k]; }
        float inv = 1.f / den;
#pragma unroll
        for (int k = 0; k < 8; k++) out[(size_t)n * 8 + k] = e[k] * inv;
    }
}

// ---------------- edge head: softmax(h[src]@edge_W+b) ----------------
__global__ void __launch_bounds__(128)
mt_edge_head(const float* __restrict__ hh, const int* __restrict__ src,
             const float* __restrict__ W, const float* __restrict__ b,
             float* __restrict__ out) {
    __shared__ float Ws[128 * 6];
    __shared__ float sb[6];
    int t = threadIdx.x, lane = t & 31, wid = t >> 5;
    for (int i = t; i < 768; i += 128) Ws[i] = W[i];
    if (t < 6) sb[t] = b[t];
    __syncthreads();
    int e = blockIdx.x * 4 + wid;
    if (e >= EE) return;
    int s = src[e];
    float4 hv = reinterpret_cast<const float4*>(hh + (size_t)s * 128)[lane];
    float a[6];
#pragma unroll
    for (int k = 0; k < 6; k++)
        a[k] = hv.x * Ws[(lane * 4 + 0) * 6 + k] + hv.y * Ws[(lane * 4 + 1) * 6 + k]
             + hv.z * Ws[(lane * 4 + 2) * 6 + k] + hv.w * Ws[(lane * 4 + 3) * 6 + k];
#pragma unroll
    for (int k = 0; k < 6; k++)
#pragma unroll
        for (int off = 16; off; off >>= 1) a[k] += __shfl_xor_sync(0xffffffffu, a[k], off);
    if (lane == 0) {
        float mx = -1e30f;
#pragma unroll
        for (int k = 0; k < 6; k++) { a[k] += sb[k]; mx = fmaxf(mx, a[k]); }
        float ev[6], den = 0.f;
#pragma unroll
        for (int k = 0; k < 6; k++) { ev[k] = __expf(a[k] - mx); den += ev[k]; }
        float inv = 1.f / den;
#pragma unroll
        for (int k = 0; k < 6; k++) out[(size_t)e * 6 + k] = ev[k] * inv;
    }
}

// ---------------- recon: h[src]@rec_W + rec_b ----------------
__global__ void __launch_bounds__(128)
mt_recon(const float* __restrict__ hh, const int* __restrict__ src,
         const float* __restrict__ W, const float* __restrict__ b,
         float* __restrict__ out) {
    __shared__ float Ws[128 * 64];              // 32KB
    __shared__ __align__(16) float As[16 * 128]; // 8KB
    __shared__ int sidx[16];
    int t = threadIdx.x;
    int c = t & 63;        // output column
    int g = t >> 6;        // row subgroup: rows g*8 .. g*8+7
    for (int i = t; i < 128 * 64; i += 128) Ws[i] = W[i];
    float bv = b[c];
    int ntiles = (EE + 15) >> 4;
    for (int tt = blockIdx.x; tt < ntiles; tt += gridDim.x) {
        int rb = tt << 4;
        int nr = min(16, EE - rb);
        __syncthreads();
        if (t < nr) sidx[t] = src[rb + t];
        __syncthreads();
        for (int i = t; i < 16 * 128; i += 128) {
            int r = i >> 7;
            As[i] = (r < nr) ? hh[(size_t)sidx[r] * 128 + (i & 127)] : 0.f;
        }
        __syncthreads();
        float acc[8];
#pragma unroll
        for (int r = 0; r < 8; r++) acc[r] = bv;
        const float4* As4 = reinterpret_cast<const float4*>(As + g * 8 * 128);
#pragma unroll 4
        for (int k4 = 0; k4 < 32; k4++) {
            float4 a[8];
#pragma unroll
            for (int r = 0; r < 8; r++) a[r] = As4[r * 32 + k4];
#pragma unroll
            for (int kk = 0; kk < 4; kk++) {
                float w = Ws[(k4 * 4 + kk) * 64 + c];
#pragma unroll
                for (int r = 0; r < 8; r++) acc[r] += f4c(a[r], kk) * w;
            }
        }
#pragma unroll
        for (int r = 0; r < 8; r++) {
            int row = g * 8 + r;
            if (row < nr) out[(size_t)(rb + row) * 64 + c] = acc[r];
        }
    }
}

// ---------------- launch ----------------
extern "C" void kernel_launch(void* const* d_in, const int* in_sizes, int n_in,
                              void* d_out, int out_size) {
    const float* x     = (const float*)d_in[0];
    const float* ef    = (const float*)d_in[1];
    const int*   eidx  = (const int*)d_in[2];
    const int*   src   = eidx;
    const int*   dst   = eidx + EE;
    const float* up_W  = (const float*)d_in[3];
    const float* up_b  = (const float*)d_in[4];

    // Input ordering: setup_inputs() dict order puts the head weights
    // (node_W..rec_b) at indices 5..10 and the GAT blocks at 11..28.
    // Detect by size: node_W has 128*8=1024 elems, g0_Wl has 16384.
    bool dict_order = (in_sizes[5] == 1024);
    int iNW, iNB, iEW, iEB, iRW, iRB, iG0, iG1;
    if (dict_order) {
        iNW = 5; iNB = 6; iEW = 7; iEB = 8; iRW = 9; iRB = 10;
        iG0 = 11; iG1 = 20;
    } else {
        iG0 = 5; iG1 = 14;
        iNW = 23; iNB = 24; iEW = 25; iEB = 26; iRW = 27; iRB = 28;
    }
    const float* node_W = (const float*)d_in[iNW];
    const float* node_b = (const float*)d_in[iNB];
    const float* edge_W = (const float*)d_in[iEW];
    const float* edge_b = (const float*)d_in[iEB];
    const float* rec_W  = (const float*)d_in[iRW];
    const float* rec_b  = (const float*)d_in[iRB];
    const float* g0_Wl  = (const float*)d_in[iG0 + 0];
    const float* g0_bl  = (const float*)d_in[iG0 + 1];
    const float* g0_Wr  = (const float*)d_in[iG0 + 2];
    const float* g0_br  = (const float*)d_in[iG0 + 3];
    const float* g0_We  = (const float*)d_in[iG0 + 4];
    const float* g0_att = (const float*)d_in[iG0 + 5];
    const float* g0_bias= (const float*)d_in[iG0 + 6];
    const float* g0_ls  = (const float*)d_in[iG0 + 7];
    const float* g0_lb  = (const float*)d_in[iG0 + 8];
    const float* g1_Wl  = (const float*)d_in[iG1 + 0];
    const float* g1_bl  = (const float*)d_in[iG1 + 1];
    const float* g1_Wr  = (const float*)d_in[iG1 + 2];
    const float* g1_br  = (const float*)d_in[iG1 + 3];
    const float* g1_We  = (const float*)d_in[iG1 + 4];
    const float* g1_att = (const float*)d_in[iG1 + 5];
    const float* g1_bias= (const float*)d_in[iG1 + 6];
    const float* g1_ls  = (const float*)d_in[iG1 + 7];
    const float* g1_lb  = (const float*)d_in[iG1 + 8];

    float* out_node = (float*)d_out;
    float* out_edge = out_node + (size_t)NN * 8;
    float* out_rec  = out_edge + (size_t)EE * 6;

    float *xl, *xr, *hbuf;
    int* degp;
    cudaGetSymbolAddress((void**)&xl, g_xl);
    cudaGetSymbolAddress((void**)&xr, g_xr);
    cudaGetSymbolAddress((void**)&hbuf, g_h);
    cudaGetSymbolAddress((void**)&degp, g_deg);

    size_t sm64  = (size_t)(64 * 128 + 8 * 64) * 4;
    size_t sm128 = (size_t)(128 * 128 + 8 * 128) * 4;
    size_t smEB  = (size_t)(2 * 64 * 128 + 8 * 64) * 4;
    cudaFuncSetAttribute(mt_gemm<64>,  cudaFuncAttributeMaxDynamicSharedMemorySize, (int)sm64);
    cudaFuncSetAttribute(mt_gemm<128>, cudaFuncAttributeMaxDynamicSharedMemorySize, (int)sm128);
    cudaFuncSetAttribute(mt_edge_block0, cudaFuncAttributeMaxDynamicSharedMemorySize, (int)smEB);

    // CSR by dst (deterministic structure; order within node via atomics)
    mt_zero_int<<<(NN + 255) / 256, 256>>>(degp, NN);
    mt_hist<<<(EE + 255) / 256, 256>>>(dst, EE);
    mt_scan<<<1, 1024>>>(NN);
    mt_scatter<<<(EE + 255) / 256, 256>>>(dst, EE);

    // weight folding
    mt_combine<<<65, 128>>>(up_W, up_b, g0_Wl, g0_bl, g0_Wr, g0_br, g0_We, g1_We);

    // block 0
    mt_gemm<64><<<888, 128, sm64>>>(x, nullptr, nullptr, 0, xl, NN);
    mt_gemm<64><<<888, 128, sm64>>>(x, nullptr, nullptr, 1, xr, NN);
    mt_edge_block0<<<444, 128, smEB>>>(ef, src, dst, g0_att);
    mt_softmax_stats<<<(NN + 15) / 16, 128>>>();
    mt_alpha<<<(EE * 8 + 255) / 256, 256>>>(dst);
    mt_aggregate<<<NN, 128>>>(src, g0_bias, g0_ls, g0_lb, xl, hbuf);

    // block 1
    mt_gemm<128><<<444, 128, sm128>>>(hbuf, g1_Wl, g1_bl, 0, xl, NN);
    mt_gemm<128><<<444, 128, sm128>>>(hbuf, g1_Wr, g1_br, 0, xr, NN);
    mt_edge_logits1<<<(EE + 7) / 8, 128>>>(src, dst, g1_att);
    mt_softmax_stats<<<(NN + 15) / 16, 128>>>();
    mt_alpha<<<(EE * 8 + 255) / 256, 256>>>(dst);
    mt_aggregate<<<NN, 128>>>(src, g1_bias, g1_ls, g1_lb, xl, hbuf);

    // heads
    mt_node_head<<<(NN + 3) / 4, 128>>>(hbuf, node_W, node_b, out_node);
    mt_edge_head<<<(EE + 3) / 4, 128>>>(hbuf, src, edge_W, edge_b, out_edge);
    mt_recon<<<740, 128>>>(hbuf, src, rec_W, rec_b, out_rec);
}

// round 9
// speedup vs baseline: 1.2027x; 1.2027x over previous
#include <cuda_runtime.h>
#include <math.h>

#define NN 50000
#define EE 800000
#define NEG 0.2f
typedef unsigned long long u64;

// ---------------- static device scratch (no allocations) ----------------
__device__ __align__(16) float g_xl[(size_t)NN * 128];
__device__ __align__(16) float g_xr[(size_t)NN * 128];
__device__ __align__(16) float g_h [(size_t)NN * 128];
__device__ __align__(16) float g_em1[(size_t)EE * 128];
__device__ __align__(16) float g_alpha[(size_t)EE * 8];   // logits (pre-softmax)
__device__ float g_mx[NN * 8];
__device__ float g_den[NN * 8];
__device__ int   g_rowptr[NN + 1];
__device__ int   g_deg[NN];
__device__ int   g_perm[EE];
__device__ __align__(16) float g_cw[4 * 64 * 128];  // up_W@{Wl0,Wr0,We0,We1}
__device__ float g_cb[4 * 128];

// ---------------- f32x2 packed math helpers ----------------
__device__ __forceinline__ u64 pk2(float lo, float hi) {
    u64 r; asm("mov.b64 %0, {%1, %2};" : "=l"(r) : "f"(lo), "f"(hi)); return r;
}
__device__ __forceinline__ void upk2(u64 v, float& lo, float& hi) {
    asm("mov.b64 {%0, %1}, %2;" : "=f"(lo), "=f"(hi) : "l"(v));
}
#define FMA2(d, a, b) asm("fma.rn.f32x2 %0, %1, %2, %0;" : "+l"(d) : "l"(a), "l"(b))

// ---------------- CSR build ----------------
__global__ void mt_zero_int(int* p, int n) {
    int i = blockIdx.x * blockDim.x + threadIdx.x;
    if (i < n) p[i] = 0;
}
__global__ void mt_hist(const int* __restrict__ dst, int e) {
    int i = blockIdx.x * blockDim.x + threadIdx.x;
    if (i < e) atomicAdd(&g_deg[dst[i]], 1);
}
__global__ void mt_scan(int n) {
    __shared__ int sh[1024];
    int t = threadIdx.x;
    int carry = 0;
    for (int base = 0; base < n; base += 1024) {
        int idx = base + t;
        int v = (idx < n) ? g_deg[idx] : 0;
        sh[t] = v;
        __syncthreads();
        for (int off = 1; off < 1024; off <<= 1) {
            int u = (t >= off) ? sh[t - off] : 0;
            __syncthreads();
            sh[t] += u;
            __syncthreads();
        }
        if (idx < n) {
            int excl = sh[t] - v;
            g_rowptr[idx] = carry + excl;
            g_deg[idx]    = carry + excl;
        }
        carry += sh[1023];
        __syncthreads();
    }
    if (t == 0) g_rowptr[n] = carry;
}
__global__ void mt_scatter(const int* __restrict__ dst, int e) {
    int i = blockIdx.x * blockDim.x + threadIdx.x;
    if (i < e) {
        int p = atomicAdd(&g_deg[dst[i]], 1);
        g_perm[p] = i;
    }
}

// ---------------- fold up_W into block weights ----------------
__global__ void mt_combine(const float* __restrict__ up_W, const float* __restrict__ up_b,
                           const float* __restrict__ Wl0, const float* __restrict__ bl0,
                           const float* __restrict__ Wr0, const float* __restrict__ br0,
                           const float* __restrict__ We0, const float* __restrict__ We1) {
    __shared__ float row[128];
    int c = threadIdx.x;
    int k = blockIdx.x;
    if (k < 64) {
        row[c] = up_W[k * 128 + c];
        __syncthreads();
        float a0 = 0.f, a1 = 0.f, a2 = 0.f, a3 = 0.f;
        for (int j = 0; j < 128; j++) {
            float r = row[j];
            a0 += r * Wl0[j * 128 + c];
            a1 += r * Wr0[j * 128 + c];
            a2 += r * We0[j * 128 + c];
            a3 += r * We1[j * 128 + c];
        }
        g_cw[0 * 64 * 128 + k * 128 + c] = a0;
        g_cw[1 * 64 * 128 + k * 128 + c] = a1;
        g_cw[2 * 64 * 128 + k * 128 + c] = a2;
        g_cw[3 * 64 * 128 + k * 128 + c] = a3;
    } else {
        float a0 = 0.f, a1 = 0.f, a2 = 0.f, a3 = 0.f;
        for (int j = 0; j < 128; j++) {
            float ub = up_b[j];
            a0 += ub * Wl0[j * 128 + c];
            a1 += ub * Wr0[j * 128 + c];
            a2 += ub * We0[j * 128 + c];
            a3 += ub * We1[j * 128 + c];
        }
        g_cb[0 * 128 + c] = a0 + bl0[c];
        g_cb[1 * 128 + c] = a1 + br0[c];
        g_cb[2 * 128 + c] = a2;
        g_cb[3 * 128 + c] = a3;
    }
}

// ---------------- fused lin0: xl0 & xr0 = x @ {cw0,cw1} + cb (K=64, FFMA2) ----------------
__global__ void __launch_bounds__(128)
mt_lin0(const float* __restrict__ x) {
    extern __shared__ float sm[];
    float* W0 = sm;                 // 64*128
    float* W1 = sm + 64 * 128;      // 64*128
    float* Ad = sm + 2 * 64 * 128;  // 16 rows * 64k dup = 16*128 floats
    int t = threadIdx.x;
    int c = t & 63, g = t >> 6;
    for (int i = t; i < 64 * 128; i += 128) { W0[i] = g_cw[i]; W1[i] = g_cw[64 * 128 + i]; }
    u64 b0 = pk2(g_cb[2 * c], g_cb[2 * c + 1]);
    u64 b1 = pk2(g_cb[128 + 2 * c], g_cb[128 + 2 * c + 1]);
    const float2* x2 = (const float2*)x;
    float4* Ad4 = (float4*)Ad;
    const ulonglong2* Ad2 = (const ulonglong2*)Ad;
    for (int tt = blockIdx.x; tt < NN / 16; tt += gridDim.x) {
        int rb = tt * 16;
        __syncthreads();
        for (int i = t; i < 16 * 32; i += 128) {
            float2 v = x2[(size_t)(rb + (i >> 5)) * 32 + (i & 31)];
            Ad4[i] = make_float4(v.x, v.x, v.y, v.y);
        }
        __syncthreads();
        u64 a0[8], a1[8];
#pragma unroll
        for (int r = 0; r < 8; r++) { a0[r] = b0; a1[r] = b1; }
#pragma unroll 4
        for (int k2 = 0; k2 < 32; k2++) {
            u64 w00 = *(const u64*)&W0[(2 * k2) * 128 + 2 * c];
            u64 w01 = *(const u64*)&W0[(2 * k2 + 1) * 128 + 2 * c];
            u64 w10 = *(const u64*)&W1[(2 * k2) * 128 + 2 * c];
            u64 w11 = *(const u64*)&W1[(2 * k2 + 1) * 128 + 2 * c];
#pragma unroll
            for (int r = 0; r < 8; r++) {
                ulonglong2 av = Ad2[(g * 8 + r) * 32 + k2];
                FMA2(a0[r], av.x, w00); FMA2(a0[r], av.y, w01);
                FMA2(a1[r], av.x, w10); FMA2(a1[r], av.y, w11);
            }
        }
#pragma unroll
        for (int r = 0; r < 8; r++) {
            float lo, hi;
            size_t off = (size_t)(rb + g * 8 + r) * 128 + 2 * c;
            upk2(a0[r], lo, hi);
            *(float2*)&g_xl[off] = make_float2(lo, hi);
            upk2(a1[r], lo, hi);
            *(float2*)&g_xr[off] = make_float2(lo, hi);
        }
    }
}

// ---------------- fused block-0 edge kernel: em0->logits, em1 stored (FFMA2) ----------------
__global__ void __launch_bounds__(128)
mt_edge_block0(const float* __restrict__ ef, const int* __restrict__ src,
               const int* __restrict__ dst, const float* __restrict__ att) {
    extern __shared__ float sm[];
    float* WA = sm;                 // cw2
    float* WB = sm + 64 * 128;      // cw3
    float* Ad = sm + 2 * 64 * 128;  // 16*128 dup
    __shared__ float s_att[128];
    __shared__ int sidx[16], didx[16];
    int t = threadIdx.x;
    int c = t & 63, g = t >> 6;
    for (int i = t; i < 64 * 128; i += 128) {
        WA[i] = g_cw[2 * 64 * 128 + i];
        WB[i] = g_cw[3 * 64 * 128 + i];
    }
    s_att[t] = att[t];
    u64 cb2 = pk2(g_cb[2 * 128 + 2 * c], g_cb[2 * 128 + 2 * c + 1]);
    u64 cb3 = pk2(g_cb[3 * 128 + 2 * c], g_cb[3 * 128 + 2 * c + 1]);
    float at0 = att[2 * c], at1 = att[2 * c + 1];
    const float2* ef2 = (const float2*)ef;
    float4* Ad4 = (float4*)Ad;
    const ulonglong2* Ad2 = (const ulonglong2*)Ad;
    for (int tt = blockIdx.x; tt < EE / 16; tt += gridDim.x) {
        int rb = tt * 16;
        __syncthreads();
        if (t < 16) { sidx[t] = src[rb + t]; didx[t] = dst[rb + t]; }
        for (int i = t; i < 16 * 32; i += 128) {
            float2 v = ef2[(size_t)(rb + (i >> 5)) * 32 + (i & 31)];
            Ad4[i] = make_float4(v.x, v.x, v.y, v.y);
        }
        __syncthreads();
        u64 a0[8], a1[8];
#pragma unroll
        for (int r = 0; r < 8; r++) { a0[r] = cb2; a1[r] = cb3; }
#pragma unroll 4
        for (int k2 = 0; k2 < 32; k2++) {
            u64 wA0 = *(const u64*)&WA[(2 * k2) * 128 + 2 * c];
            u64 wA1 = *(const u64*)&WA[(2 * k2 + 1) * 128 + 2 * c];
            u64 wB0 = *(const u64*)&WB[(2 * k2) * 128 + 2 * c];
            u64 wB1 = *(const u64*)&WB[(2 * k2 + 1) * 128 + 2 * c];
#pragma unroll
            for (int r = 0; r < 8; r++) {
                ulonglong2 av = Ad2[(g * 8 + r) * 32 + k2];
                FMA2(a0[r], av.x, wA0); FMA2(a0[r], av.y, wA1);
                FMA2(a1[r], av.x, wB0); FMA2(a1[r], av.y, wB1);
            }
        }
#pragma unroll
        for (int r = 0; r < 8; r++) {
            int row = g * 8 + r;
            int e = rb + row;
            float lo, hi;
            upk2(a1[r], lo, hi);
            *(float2*)&g_em1[(size_t)e * 128 + 2 * c] = make_float2(lo, hi);
            float m0, m1;
            upk2(a0[r], m0, m1);
            float2 xlv = *(const float2*)&g_xl[(size_t)sidx[row] * 128 + 2 * c];
            float2 xrv = *(const float2*)&g_xr[(size_t)didx[row] * 128 + 2 * c];
            m0 += xlv.x + xrv.x;
            m1 += xlv.y + xrv.y;
            m0 = m0 > 0.f ? m0 : NEG * m0;
            m1 = m1 > 0.f ? m1 : NEG * m1;
            float p = m0 * at0 + m1 * at1;
            p += __shfl_xor_sync(0xffffffffu, p, 1);
            p += __shfl_xor_sync(0xffffffffu, p, 2);
            p += __shfl_xor_sync(0xffffffffu, p, 4);
            if ((c & 7) == 0) g_alpha[(size_t)e * 8 + (c >> 3)] = p;
        }
    }
}

// ---------------- block-1 edge logits (memory-bound stream over em1) ----------------
__global__ void __launch_bounds__(128)
mt_edge_logits1(const int* __restrict__ src, const int* __restrict__ dst,
                const float* __restrict__ att) {
    __shared__ float s_att[128];
    __shared__ int sidx[8], didx[8];
    int c = threadIdx.x;
    s_att[c] = att[c];
    int rb = blockIdx.x * 8;
    if (c < 8) { sidx[c] = src[rb + c]; didx[c] = dst[rb + c]; }
    __syncthreads();
    float av = s_att[c];
    for (int r = 0; r < 8; r++) {
        int e = rb + r;
        float m = g_em1[(size_t)e * 128 + c] + g_xl[(size_t)sidx[r] * 128 + c]
                                             + g_xr[(size_t)didx[r] * 128 + c];
        m = m > 0.f ? m : NEG * m;
        float p = m * av;
        p += __shfl_xor_sync(0xffffffffu, p, 8, 16);
        p += __shfl_xor_sync(0xffffffffu, p, 4, 16);
        p += __shfl_xor_sync(0xffffffffu, p, 2, 16);
        p += __shfl_xor_sync(0xffffffffu, p, 1, 16);
        if ((c & 15) == 0) g_alpha[(size_t)e * 8 + (c >> 4)] = p;
    }
}

// ---------------- segment softmax stats: per-(node,head) online max+den ----------------
__global__ void mt_softmax_stats() {
    int t = threadIdx.x;
    int n = blockIdx.x * 16 + (t >> 3);
    int h = t & 7;
    if (n >= NN) return;
    int beg = g_rowptr[n], end = g_rowptr[n + 1];
    float mx = -1e30f, den = 0.f;
    for (int j = beg; j < end; j++) {
        int e = g_perm[j];
        float lg = g_alpha[(size_t)e * 8 + h];
        if (lg > mx) { den *= __expf(mx - lg); mx = lg; }
        den += __expf(lg - mx);
    }
    g_mx[n * 8 + h] = mx;
    g_den[n * 8 + h] = den;
}

// ---------------- aggregate (alpha fused) + bias + LayerNorm + ReLU ----------------
__global__ void __launch_bounds__(128)
mt_aggregate(const int* __restrict__ src, const float* __restrict__ bias,
             const float* __restrict__ ls, const float* __restrict__ lb,
             const float* __restrict__ xl, float* __restrict__ out) {
    __shared__ int sidx[16];
    __shared__ int eidx[16];
    __shared__ float sal[16 * 8];
    __shared__ float red[8];
    __shared__ float s_mx[8], s_inv[8];
    int n = blockIdx.x;
    int c = threadIdx.x;
    int h = c >> 4;
    if (c < 8) { s_mx[c] = g_mx[n * 8 + c]; s_inv[c] = 1.f / g_den[n * 8 + c]; }
    int beg = g_rowptr[n], cnt = g_rowptr[n + 1] - beg;
    float acc = 0.f;
    for (int off = 0; off < cnt; off += 16) {
        int cl = min(16, cnt - off);
        __syncthreads();
        if (c < cl) {
            int e = g_perm[beg + off + c];
            eidx[c] = e;
            sidx[c] = src[e];
        }
        __syncthreads();
        if ((c >> 3) < cl) {
            int hh = c & 7;
            float lg = g_alpha[(size_t)eidx[c >> 3] * 8 + hh];
            sal[c] = __expf(lg - s_mx[hh]) * s_inv[hh];
        }
        __syncthreads();
        for (int i = 0; i < cl; i++)
            acc += sal[i * 8 + h] * xl[(size_t)sidx[i] * 128 + c];
    }
    float o = acc + bias[c];
    float s1 = o, s2 = o * o;
#pragma unroll
    for (int off = 16; off; off >>= 1) {
        s1 += __shfl_xor_sync(0xffffffffu, s1, off);
        s2 += __shfl_xor_sync(0xffffffffu, s2, off);
    }
    if ((c & 31) == 0) { red[c >> 5] = s1; red[4 + (c >> 5)] = s2; }
    __syncthreads();
    s1 = red[0] + red[1] + red[2] + red[3];
    s2 = red[4] + red[5] + red[6] + red[7];
    float mu = s1 * (1.f / 128.f);
    float var = s2 * (1.f / 128.f) - mu * mu;
    o = (o - mu) * rsqrtf(var + 1e-5f) * ls[c] + lb[c];
    out[(size_t)n * 128 + c] = fmaxf(o, 0.f);
}

// ---------------- block-1 node GEMM: out = in[N,128]@W + b (FFMA2) ----------------
__global__ void __launch_bounds__(128)
mt_gemm128(const float* __restrict__ in, const float* __restrict__ W,
           const float* __restrict__ bias, float* __restrict__ out) {
    extern __shared__ float sm[];
    float* Ws = sm;             // 128*128
    float* Ad = sm + 128 * 128; // 16*256 dup
    int t = threadIdx.x;
    int c = t & 63, g = t >> 6;
    for (int i = t; i < 128 * 128; i += 128) Ws[i] = W[i];
    u64 bv = pk2(bias[2 * c], bias[2 * c + 1]);
    const float2* in2 = (const float2*)in;
    float4* Ad4 = (float4*)Ad;
    const ulonglong2* Ad2 = (const ulonglong2*)Ad;
    for (int tt = blockIdx.x; tt < NN / 16; tt += gridDim.x) {
        int rb = tt * 16;
        __syncthreads();
        for (int i = t; i < 16 * 64; i += 128) {
            float2 v = in2[(size_t)(rb + (i >> 6)) * 64 + (i & 63)];
            Ad4[i] = make_float4(v.x, v.x, v.y, v.y);
        }
        __syncthreads();
        u64 acc[8];
#pragma unroll
        for (int r = 0; r < 8; r++) acc[r] = bv;
#pragma unroll 4
        for (int k2 = 0; k2 < 64; k2++) {
            u64 w0 = *(const u64*)&Ws[(2 * k2) * 128 + 2 * c];
            u64 w1 = *(const u64*)&Ws[(2 * k2 + 1) * 128 + 2 * c];
#pragma unroll
            for (int r = 0; r < 8; r++) {
                ulonglong2 av = Ad2[(g * 8 + r) * 64 + k2];
                FMA2(acc[r], av.x, w0); FMA2(acc[r], av.y, w1);
            }
        }
#pragma unroll
        for (int r = 0; r < 8; r++) {
            float lo, hi;
            upk2(acc[r], lo, hi);
            *(float2*)&out[(size_t)(rb + g * 8 + r) * 128 + 2 * c] = make_float2(lo, hi);
        }
    }
}

// ---------------- node head: softmax(h@node_W+b) ----------------
__global__ void __launch_bounds__(128)
mt_node_head(const float* __restrict__ hh, const float* __restrict__ W,
             const float* __restrict__ b, float* __restrict__ out) {
    __shared__ float Ws[128 * 8];
    __shared__ float sb[8];
    int t = threadIdx.x, lane = t & 31, wid = t >> 5;
    for (int i = t; i < 1024; i += 128) Ws[i] = W[i];
    if (t < 8) sb[t] = b[t];
    __syncthreads();
    int n = blockIdx.x * 4 + wid;
    if (n >= NN) return;
    float4 hv = reinterpret_cast<const float4*>(hh + (size_t)n * 128)[lane];
    float a[8];
#pragma unroll
    for (int k = 0; k < 8; k++)
        a[k] = hv.x * Ws[(lane * 4 + 0) * 8 + k] + hv.y * Ws[(lane * 4 + 1) * 8 + k]
             + hv.z * Ws[(lane * 4 + 2) * 8 + k] + hv.w * Ws[(lane * 4 + 3) * 8 + k];
#pragma unroll
    for (int k = 0; k < 8; k++)
#pragma unroll
        for (int off = 16; off; off >>= 1) a[k] += __shfl_xor_sync(0xffffffffu, a[k], off);
    if (lane == 0) {
        float mx = -1e30f;
#pragma unroll
        for (int k = 0; k < 8; k++) { a[k] += sb[k]; mx = fmaxf(mx, a[k]); }
        float e[8], den = 0.f;
#pragma unroll
        for (int k = 0; k < 8; k++) { e[k] = __expf(a[k] - mx); den += e[k]; }
        float inv = 1.f / den;
#pragma unroll
        for (int k = 0; k < 8; k++) out[(size_t)n * 8 + k] = e[k] * inv;
    }
}

// ---------------- edge head: softmax(h[src]@edge_W+b) ----------------
__global__ void __launch_bounds__(128)
mt_edge_head(const float* __restrict__ hh, const int* __restrict__ src,
             const float* __restrict__ W, const float* __restrict__ b,
             float* __restrict__ out) {
    __shared__ float Ws[128 * 6];
    __shared__ float sb[6];
    int t = threadIdx.x, lane = t & 31, wid = t >> 5;
    for (int i = t; i < 768; i += 128) Ws[i] = W[i];
    if (t < 6) sb[t] = b[t];
    __syncthreads();
    int e = blockIdx.x * 4 + wid;
    if (e >= EE) return;
    int s = src[e];
    float4 hv = reinterpret_cast<const float4*>(hh + (size_t)s * 128)[lane];
    float a[6];
#pragma unroll
    for (int k = 0; k < 6; k++)
        a[k] = hv.x * Ws[(lane * 4 + 0) * 6 + k] + hv.y * Ws[(lane * 4 + 1) * 6 + k]
             + hv.z * Ws[(lane * 4 + 2) * 6 + k] + hv.w * Ws[(lane * 4 + 3) * 6 + k];
#pragma unroll
    for (int k = 0; k < 6; k++)
#pragma unroll
        for (int off = 16; off; off >>= 1) a[k] += __shfl_xor_sync(0xffffffffu, a[k], off);
    if (lane == 0) {
        float mx = -1e30f;
#pragma unroll
        for (int k = 0; k < 6; k++) { a[k] += sb[k]; mx = fmaxf(mx, a[k]); }
        float ev[6], den = 0.f;
#pragma unroll
        for (int k = 0; k < 6; k++) { ev[k] = __expf(a[k] - mx); den += ev[k]; }
        float inv = 1.f / den;
#pragma unroll
        for (int k = 0; k < 6; k++) out[(size_t)e * 6 + k] = ev[k] * inv;
    }
}

// ---------------- recon: h[src]@rec_W + rec_b (FFMA2, 32 edges/tile) ----------------
__global__ void __launch_bounds__(128)
mt_recon(const float* __restrict__ hh, const int* __restrict__ src,
         const float* __restrict__ W, const float* __restrict__ b,
         float* __restrict__ out) {
    extern __shared__ float sm[];
    float* Ws = sm;             // 128*64
    float* Ad = sm + 128 * 64;  // 32 rows * 128k dup = 32*256 floats
    __shared__ int sidx[32];
    int t = threadIdx.x;
    int c = t & 31, g = t >> 5;  // 32 col-pairs, 4 row groups of 8
    for (int i = t; i < 128 * 64; i += 128) Ws[i] = W[i];
    u64 bv = pk2(b[2 * c], b[2 * c + 1]);
    const float2* h2 = (const float2*)hh;
    float4* Ad4 = (float4*)Ad;
    const ulonglong2* Ad2 = (const ulonglong2*)Ad;
    for (int tt = blockIdx.x; tt < EE / 32; tt += gridDim.x) {
        int rb = tt * 32;
        __syncthreads();
        if (t < 32) sidx[t] = src[rb + t];
        __syncthreads();
        for (int i = t; i < 32 * 64; i += 128) {
            float2 v = h2[(size_t)sidx[i >> 6] * 64 + (i & 63)];
            Ad4[i] = make_float4(v.x, v.x, v.y, v.y);
        }
        __syncthreads();
        u64 acc[8];
#pragma unroll
        for (int r = 0; r < 8; r++) acc[r] = bv;
#pragma unroll 4
        for (int k2 = 0; k2 < 64; k2++) {
            u64 w0 = *(const u64*)&Ws[(2 * k2) * 64 + 2 * c];
            u64 w1 = *(const u64*)&Ws[(2 * k2 + 1) * 64 + 2 * c];
#pragma unroll
            for (int r = 0; r < 8; r++) {
                ulonglong2 av = Ad2[(g * 8 + r) * 64 + k2];
                FMA2(acc[r], av.x, w0); FMA2(acc[r], av.y, w1);
            }
        }
#pragma unroll
        for (int r = 0; r < 8; r++) {
            float lo, hi;
            upk2(acc[r], lo, hi);
            *(float2*)&out[(size_t)(rb + g * 8 + r) * 64 + 2 * c] = make_float2(lo, hi);
        }
    }
}

// ---------------- launch ----------------
extern "C" void kernel_launch(void* const* d_in, const int* in_sizes, int n_in,
                              void* d_out, int out_size) {
    const float* x     = (const float*)d_in[0];
    const float* ef    = (const float*)d_in[1];
    const int*   eidx  = (const int*)d_in[2];
    const int*   src   = eidx;
    const int*   dst   = eidx + EE;
    const float* up_W  = (const float*)d_in[3];
    const float* up_b  = (const float*)d_in[4];

    // dict-order vs signature-order detection (node_W = 1024 elems)
    bool dict_order = (in_sizes[5] == 1024);
    int iNW, iNB, iEW, iEB, iRW, iRB, iG0, iG1;
    if (dict_order) {
        iNW = 5; iNB = 6; iEW = 7; iEB = 8; iRW = 9; iRB = 10;
        iG0 = 11; iG1 = 20;
    } else {
        iG0 = 5; iG1 = 14;
        iNW = 23; iNB = 24; iEW = 25; iEB = 26; iRW = 27; iRB = 28;
    }
    const float* node_W = (const float*)d_in[iNW];
    const float* node_b = (const float*)d_in[iNB];
    const float* edge_W = (const float*)d_in[iEW];
    const float* edge_b = (const float*)d_in[iEB];
    const float* rec_W  = (const float*)d_in[iRW];
    const float* rec_b  = (const float*)d_in[iRB];
    const float* g0_Wl  = (const float*)d_in[iG0 + 0];
    const float* g0_bl  = (const float*)d_in[iG0 + 1];
    const float* g0_Wr  = (const float*)d_in[iG0 + 2];
    const float* g0_br  = (const float*)d_in[iG0 + 3];
    const float* g0_We  = (const float*)d_in[iG0 + 4];
    const float* g0_att = (const float*)d_in[iG0 + 5];
    const float* g0_bias= (const float*)d_in[iG0 + 6];
    const float* g0_ls  = (const float*)d_in[iG0 + 7];
    const float* g0_lb  = (const float*)d_in[iG0 + 8];
    const float* g1_Wl  = (const float*)d_in[iG1 + 0];
    const float* g1_bl  = (const float*)d_in[iG1 + 1];
    const float* g1_Wr  = (const float*)d_in[iG1 + 2];
    const float* g1_br  = (const float*)d_in[iG1 + 3];
    const float* g1_We  = (const float*)d_in[iG1 + 4];
    const float* g1_att = (const float*)d_in[iG1 + 5];
    const float* g1_bias= (const float*)d_in[iG1 + 6];
    const float* g1_ls  = (const float*)d_in[iG1 + 7];
    const float* g1_lb  = (const float*)d_in[iG1 + 8];

    float* out_node = (float*)d_out;
    float* out_edge = out_node + (size_t)NN * 8;
    float* out_rec  = out_edge + (size_t)EE * 6;

    float *xl, *xr, *hbuf;
    int* degp;
    cudaGetSymbolAddress((void**)&xl, g_xl);
    cudaGetSymbolAddress((void**)&xr, g_xr);
    cudaGetSymbolAddress((void**)&hbuf, g_h);
    cudaGetSymbolAddress((void**)&degp, g_deg);

    size_t smL0 = (size_t)(2 * 64 * 128 + 16 * 128) * 4;   // 72KB
    size_t smEB = smL0;                                     // 72KB
    size_t smG  = (size_t)(128 * 128 + 16 * 256) * 4;       // 80KB
    size_t smR  = (size_t)(128 * 64 + 32 * 256) * 4;        // 64KB
    cudaFuncSetAttribute(mt_lin0,        cudaFuncAttributeMaxDynamicSharedMemorySize, (int)smL0);
    cudaFuncSetAttribute(mt_edge_block0, cudaFuncAttributeMaxDynamicSharedMemorySize, (int)smEB);
    cudaFuncSetAttribute(mt_gemm128,     cudaFuncAttributeMaxDynamicSharedMemorySize, (int)smG);
    cudaFuncSetAttribute(mt_recon,       cudaFuncAttributeMaxDynamicSharedMemorySize, (int)smR);

    // CSR by dst
    mt_zero_int<<<(NN + 255) / 256, 256>>>(degp, NN);
    mt_hist<<<(EE + 255) / 256, 256>>>(dst, EE);
    mt_scan<<<1, 1024>>>(NN);
    mt_scatter<<<(EE + 255) / 256, 256>>>(dst, EE);

    // weight folding
    mt_combine<<<65, 128>>>(up_W, up_b, g0_Wl, g0_bl, g0_Wr, g0_br, g0_We, g1_We);

    // block 0
    mt_lin0<<<444, 128, smL0>>>(x);
    mt_edge_block0<<<444, 128, smEB>>>(ef, src, dst, g0_att);
    mt_softmax_stats<<<(NN + 15) / 16, 128>>>();
    mt_aggregate<<<NN, 128>>>(src, g0_bias, g0_ls, g0_lb, xl, hbuf);

    // block 1
    mt_gemm128<<<296, 128, smG>>>(hbuf, g1_Wl, g1_bl, xl);
    mt_gemm128<<<296, 128, smG>>>(hbuf, g1_Wr, g1_br, xr);
    mt_edge_logits1<<<EE / 8, 128>>>(src, dst, g1_att);
    mt_softmax_stats<<<(NN + 15) / 16, 128>>>();
    mt_aggregate<<<NN, 128>>>(src, g1_bias, g1_ls, g1_lb, xl, hbuf);

    // heads
    mt_node_head<<<(NN + 3) / 4, 128>>>(hbuf, node_W, node_b, out_node);
    mt_edge_head<<<(EE + 3) / 4, 128>>>(hbuf, src, edge_W, edge_b, out_edge);
    mt_recon<<<444, 128, smR>>>(hbuf, src, rec_W, rec_b, out_rec);
}